// round 1
// baseline (speedup 1.0000x reference)
#include <cuda_runtime.h>
#include <math.h>

#define EPSV 1e-5f
#define SLOPE 0.2f
#define BB 4
#define NN 4096
#define KNN 10
#define K1 11
#define SSPLIT 4
#define MTOT (BB*NN)

// ---------------- scratch (device globals; no allocation allowed) ----------------
__device__ float g_cat[MTOT*512];     // concat of o1..o4 (cols 0:64,64:128,128:256,256:512)
__device__ float g_ya[MTOT*256];
__device__ float g_yc[MTOT*256];
__device__ float g_h5[MTOT*1024];
__device__ float g_sq[MTOT];
__device__ int   g_idx[MTOT*KNN];
__device__ float g_pd[(size_t)MTOT*SSPLIT*K1];
__device__ int   g_pi[(size_t)MTOT*SSPLIT*K1];
__device__ float g_wc[256*128];
__device__ float g_pmax[BB*16*1024];
__device__ float g_pool[BB*1024];
__device__ float g_f1[BB*512];
__device__ float g_f2[BB*256];

// ---------------- squared norms ----------------
__global__ void norms_kernel(const float* __restrict__ x, int ld, int D, float* __restrict__ sq) {
    int row  = blockIdx.x * (blockDim.x >> 5) + (threadIdx.x >> 5);
    int lane = threadIdx.x & 31;
    if (row >= MTOT) return;
    const float* xr = x + (size_t)row * ld;
    float s = 0.f;
    for (int d = lane; d < D; d += 32) { float v = xr[d]; s += v * v; }
    #pragma unroll
    for (int o = 16; o; o >>= 1) s += __shfl_xor_sync(0xffffffffu, s, o);
    if (lane == 0) sq[row] = s;
}

// ---------------- kNN: partial top-11 over an m-range ----------------
template<int D>
__global__ __launch_bounds__(128) void knn_partial(
    const float* __restrict__ x, int ld, const float* __restrict__ sq,
    float* __restrict__ pd, int* __restrict__ pi)
{
    const int TM = 64;
    __shared__ float tile[TM * D];
    __shared__ float sqs[TM];

    int b = blockIdx.y, z = blockIdx.z;
    int n = blockIdx.x * 128 + threadIdx.x;
    int row = b * NN + n;

    float q[D];
    {
        const float* xr = x + (size_t)row * ld;
        #pragma unroll
        for (int d = 0; d < D; d++) q[d] = xr[d];
    }
    float sqn = sq[row];

    float best[K1]; int bidx[K1];
    #pragma unroll
    for (int j = 0; j < K1; j++) { best[j] = 3e38f; bidx[j] = 0; }
    float kth = 3e38f;

    const int len = NN / SSPLIT;
    const int m0 = z * len;

    for (int t0 = m0; t0 < m0 + len; t0 += TM) {
        __syncthreads();
        if ((D & 3) == 0) {
            const int NF4 = TM * D / 4;
            for (int e = threadIdx.x; e < NF4; e += 128) {
                int mm = e / (D / 4), c4 = e % (D / 4);
                float4 v = *(const float4*)(x + (size_t)(b * NN + t0 + mm) * ld + c4 * 4);
                *(float4*)(tile + mm * D + c4 * 4) = v;
            }
        } else {
            for (int e = threadIdx.x; e < TM * D; e += 128) {
                int mm = e / D, c = e % D;
                tile[mm * D + c] = x[(size_t)(b * NN + t0 + mm) * ld + c];
            }
        }
        if (threadIdx.x < TM) sqs[threadIdx.x] = sq[b * NN + t0 + threadIdx.x];
        __syncthreads();

        for (int mm = 0; mm < TM; mm++) {
            float acc = 0.f;
            if ((D & 3) == 0) {
                #pragma unroll
                for (int d = 0; d < D; d += 4) {
                    float4 v = *(const float4*)(tile + mm * D + d);
                    acc += q[d] * v.x; acc += q[d+1] * v.y;
                    acc += q[d+2] * v.z; acc += q[d+3] * v.w;
                }
            } else {
                #pragma unroll
                for (int d = 0; d < D; d++) acc += q[d] * tile[mm * D + d];
            }
            int m = t0 + mm;
            float d2 = sqn + sqs[mm] - 2.f * acc;
            if (m == n) d2 = -3e38f;     // self is always rank 0 (matches idx[:, :, 1:])
            if (d2 < kth) {              // strict <: ties keep smaller index (top_k rule)
                int j = K1 - 1;
                while (j > 0 && d2 < best[j - 1]) {
                    best[j] = best[j - 1]; bidx[j] = bidx[j - 1]; j--;
                }
                best[j] = d2; bidx[j] = m;
                kth = best[K1 - 1];
            }
        }
    }
    size_t base = ((size_t)row * SSPLIT + z) * K1;
    for (int j = 0; j < K1; j++) { pd[base + j] = best[j]; pi[base + j] = bidx[j]; }
}

// ---------------- kNN: merge S partial lists ----------------
__global__ void knn_merge(const float* __restrict__ pd, const int* __restrict__ pi,
                          int* __restrict__ idx) {
    int row = blockIdx.x * blockDim.x + threadIdx.x;
    if (row >= MTOT) return;
    float best[K1]; int bidx[K1];
    #pragma unroll
    for (int j = 0; j < K1; j++) { best[j] = 3e38f; bidx[j] = 0; }
    for (int z = 0; z < SSPLIT; z++) {
        size_t base = ((size_t)row * SSPLIT + z) * K1;
        for (int j = 0; j < K1; j++) {
            float d2 = pd[base + j];
            int m = pi[base + j];
            if (d2 < best[K1 - 1]) {
                int p = K1 - 1;
                while (p > 0 && d2 < best[p - 1]) {
                    best[p] = best[p - 1]; bidx[p] = bidx[p - 1]; p--;
                }
                best[p] = d2; bidx[p] = m;
            }
        }
    }
    for (int j = 1; j < K1; j++) idx[row * KNN + (j - 1)] = bidx[j];
}

// ---------------- wc = w[:, D:2D] - w[:, 0:D] ----------------
__global__ void wc_kernel(const float* __restrict__ w, int O, int D, float* __restrict__ out) {
    int e = blockIdx.x * 256 + threadIdx.x;
    if (e < O * D) {
        int o = e / D, d = e % D;
        out[e] = w[o * 2 * D + D + d] - w[o * 2 * D + d];
    }
}

// ---------------- generic fp32 GEMM: C[M,Nc] = A[M,K] * B[Nc,K]^T ----------------
// EPI 0: raw store. EPI 1: lrelu(acc * (g/sqrt(1+eps)) + bt).
#define GBM 128
#define GBN 128
#define GBK 16
template<int EPI>
__global__ __launch_bounds__(256) void gemm_tn(
    const float* __restrict__ A, int lda,
    const float* __restrict__ Bm, int ldb,
    float* __restrict__ C, int ldc,
    int M, int Nc, int K,
    const float* __restrict__ gam, const float* __restrict__ bet)
{
    __shared__ float As[GBK][GBM + 4];
    __shared__ float Bs[GBK][GBN + 4];
    int t = threadIdx.x;
    int tx = t & 15, ty = t >> 4;        // 16 x 16 threads, 8x8 micro-tile
    int row0 = blockIdx.y * GBM, col0 = blockIdx.x * GBN;

    float acc[8][8];
    #pragma unroll
    for (int i = 0; i < 8; i++)
        #pragma unroll
        for (int j = 0; j < 8; j++) acc[i][j] = 0.f;

    for (int k0 = 0; k0 < K; k0 += GBK) {
        #pragma unroll
        for (int i = 0; i < 8; i++) {
            int e = t + i * 256;
            int r = e >> 4, c = e & 15;
            float v = 0.f;
            if (k0 + c < K) v = A[(size_t)(row0 + r) * lda + k0 + c];
            As[c][r] = v;
        }
        #pragma unroll
        for (int i = 0; i < 8; i++) {
            int e = t + i * 256;
            int r = e >> 4, c = e & 15;
            float v = 0.f;
            if (k0 + c < K && col0 + r < Nc) v = Bm[(size_t)(col0 + r) * ldb + k0 + c];
            Bs[c][r] = v;
        }
        __syncthreads();
        #pragma unroll
        for (int kk = 0; kk < GBK; kk++) {
            float a[8], bv[8];
            #pragma unroll
            for (int i = 0; i < 8; i++) a[i] = As[kk][ty * 8 + i];
            #pragma unroll
            for (int j = 0; j < 8; j++) bv[j] = Bs[kk][tx * 8 + j];
            #pragma unroll
            for (int i = 0; i < 8; i++)
                #pragma unroll
                for (int j = 0; j < 8; j++) acc[i][j] += a[i] * bv[j];
        }
        __syncthreads();
    }

    const float inv = 1.0f / sqrtf(1.0f + EPSV);
    #pragma unroll
    for (int j = 0; j < 8; j++) {
        int c = col0 + tx * 8 + j;
        if (c >= Nc) continue;
        float sc = 1.f, bi = 0.f;
        if (EPI == 1) { sc = gam[c] * inv; bi = bet[c]; }
        #pragma unroll
        for (int i = 0; i < 8; i++) {
            int r = row0 + ty * 8 + i;
            float v = acc[i][j];
            if (EPI == 1) { v = v * sc + bi; v = v > 0.f ? v : SLOPE * v; }
            C[(size_t)r * ldc + c] = v;
        }
    }
}

// ---------------- edge aggregate: gather + add + affine + lrelu + max_k ----------------
__global__ void aggregate_kernel(const float* __restrict__ ya, const float* __restrict__ yc,
                                 const int* __restrict__ idx,
                                 const float* __restrict__ g, const float* __restrict__ bt,
                                 float* __restrict__ out, int O, int col0)
{
    int row = blockIdx.x;
    int b = row / NN;
    int o = threadIdx.x;
    __shared__ int sidx[KNN];
    if (threadIdx.x < KNN) sidx[threadIdx.x] = idx[row * KNN + threadIdx.x];
    __syncthreads();
    float cv = yc[(size_t)row * O + o];
    float sc = g[o] * (1.0f / sqrtf(1.0f + EPSV));
    float bi = bt[o];
    float best = -3e38f;
    #pragma unroll
    for (int j = 0; j < KNN; j++) {
        float v = ya[(size_t)(b * NN + sidx[j]) * O + o] + cv;
        v = v * sc + bi;
        v = v > 0.f ? v : SLOPE * v;
        best = fmaxf(best, v);
    }
    out[(size_t)row * 512 + col0 + o] = best;
}

// ---------------- max pool over N (two stages) ----------------
__global__ void maxpool1(const float* __restrict__ h, float* __restrict__ pm) {
    int b = blockIdx.z, s = blockIdx.y;
    int o = blockIdx.x * 256 + threadIdx.x;
    float best = -3e38f;
    for (int n = s * 256; n < (s + 1) * 256; n++)
        best = fmaxf(best, h[(size_t)(b * NN + n) * 1024 + o]);
    pm[(size_t)(b * 16 + s) * 1024 + o] = best;
}
__global__ void maxpool2(const float* __restrict__ pm, float* __restrict__ out) {
    int b = blockIdx.y;
    int o = blockIdx.x * 256 + threadIdx.x;
    float best = -3e38f;
    for (int s = 0; s < 16; s++)
        best = fmaxf(best, pm[(size_t)(b * 16 + s) * 1024 + o]);
    out[b * 1024 + o] = best;
}

// ---------------- small FC layers (warp per output) ----------------
// mode 0: lrelu(dot*sc+bi); mode 1: lrelu((dot+b0)*sc+bi); mode 2: dot+b0
__global__ void fc_kernel(const float* __restrict__ in, int K,
                          const float* __restrict__ W, const float* __restrict__ b0,
                          const float* __restrict__ g, const float* __restrict__ bt,
                          float* __restrict__ out, int O, int mode)
{
    int wid = (blockIdx.x * blockDim.x + threadIdx.x) >> 5;
    int lane = threadIdx.x & 31;
    if (wid >= BB * O) return;
    int b = wid / O, o = wid % O;
    const float* ir = in + b * K;
    const float* wr = W + (size_t)o * K;
    float s = 0.f;
    for (int c = lane; c < K; c += 32) s += ir[c] * wr[c];
    #pragma unroll
    for (int off = 16; off; off >>= 1) s += __shfl_xor_sync(0xffffffffu, s, off);
    if (lane == 0) {
        if (mode == 2) out[b * O + o] = s + b0[o];
        else {
            if (mode == 1) s += b0[o];
            float v = s * (g[o] * (1.0f / sqrtf(1.0f + EPSV))) + bt[o];
            out[b * O + o] = v > 0.f ? v : SLOPE * v;
        }
    }
}

// ---------------- host orchestration ----------------
static void run_edge_layer(const float* xin, int ld, int D, int O,
                           const float* w, const float* g, const float* bt, int col0,
                           float* cat, float* ya, float* yc, float* sq,
                           float* pd, int* pi, int* idx, float* wc)
{
    norms_kernel<<<MTOT / 8, 256>>>(xin, ld, D, sq);
    dim3 kg(NN / 128, BB, SSPLIT);
    if (D == 3)        knn_partial<3><<<kg, 128>>>(xin, ld, sq, pd, pi);
    else if (D == 64)  knn_partial<64><<<kg, 128>>>(xin, ld, sq, pd, pi);
    else               knn_partial<128><<<kg, 128>>>(xin, ld, sq, pd, pi);
    knn_merge<<<(MTOT + 255) / 256, 256>>>(pd, pi, idx);

    wc_kernel<<<(O * D + 255) / 256, 256>>>(w, O, D, wc);
    dim3 gg((O + GBN - 1) / GBN, MTOT / GBM);
    gemm_tn<0><<<gg, 256>>>(xin, ld, w,  2 * D, ya, O, MTOT, O, D, nullptr, nullptr);
    gemm_tn<0><<<gg, 256>>>(xin, ld, wc, D,     yc, O, MTOT, O, D, nullptr, nullptr);

    aggregate_kernel<<<MTOT, O>>>(ya, yc, idx, g, bt, cat, O, col0);
}

extern "C" void kernel_launch(void* const* d_in, const int* in_sizes, int n_in,
                              void* d_out, int out_size)
{
    // Map inputs, skipping the scalar k (size-1 entry), robust to either argument order.
    const float* T[26]; int ti = 0;
    for (int i = 0; i < n_in && ti < 26; i++) {
        if (in_sizes[i] == 1) continue;
        T[ti++] = (const float*)d_in[i];
    }
    const float* points = T[0];
    const float* w1 = T[1],  *g1 = T[2],  *b1 = T[3];
    const float* w2 = T[4],  *g2 = T[5],  *b2 = T[6];
    const float* w3 = T[7],  *g3 = T[8],  *b3 = T[9];
    const float* w4 = T[10], *g4 = T[11], *b4 = T[12];
    const float* w5 = T[13], *g5 = T[14], *b5 = T[15];
    const float* fw1 = T[16], *fg1 = T[17], *fbt1 = T[18];
    const float* fw2 = T[19], *fb2 = T[20], *fg2 = T[21], *fbt2 = T[22];
    const float* fw3 = T[23], *fb3 = T[24];

    float *cat, *ya, *yc, *h5, *sq, *pd, *wc, *pmax, *pool, *f1, *f2;
    int *idx, *pi;
    cudaGetSymbolAddress((void**)&cat,  g_cat);
    cudaGetSymbolAddress((void**)&ya,   g_ya);
    cudaGetSymbolAddress((void**)&yc,   g_yc);
    cudaGetSymbolAddress((void**)&h5,   g_h5);
    cudaGetSymbolAddress((void**)&sq,   g_sq);
    cudaGetSymbolAddress((void**)&pd,   g_pd);
    cudaGetSymbolAddress((void**)&pi,   g_pi);
    cudaGetSymbolAddress((void**)&idx,  g_idx);
    cudaGetSymbolAddress((void**)&wc,   g_wc);
    cudaGetSymbolAddress((void**)&pmax, g_pmax);
    cudaGetSymbolAddress((void**)&pool, g_pool);
    cudaGetSymbolAddress((void**)&f1,   g_f1);
    cudaGetSymbolAddress((void**)&f2,   g_f2);

    // EdgeConv 1..4 (output columns 0,64,128,256 of cat)
    run_edge_layer(points,    3,   3,   64,  w1, g1, b1, 0,   cat, ya, yc, sq, pd, pi, idx, wc);
    run_edge_layer(cat + 0,   512, 64,  64,  w2, g2, b2, 64,  cat, ya, yc, sq, pd, pi, idx, wc);
    run_edge_layer(cat + 64,  512, 64,  128, w3, g3, b3, 128, cat, ya, yc, sq, pd, pi, idx, wc);
    run_edge_layer(cat + 128, 512, 128, 256, w4, g4, b4, 256, cat, ya, yc, sq, pd, pi, idx, wc);

    // h5 = lrelu(bn(cat @ w5^T)), then global max over N
    {
        dim3 gg(1024 / GBN, MTOT / GBM);
        gemm_tn<1><<<gg, 256>>>(cat, 512, w5, 512, h5, 1024, MTOT, 1024, 512, g5, b5);
    }
    maxpool1<<<dim3(4, 16, BB), 256>>>(h5, pmax);
    maxpool2<<<dim3(4, BB), 256>>>(pmax, pool);

    // FC head
    fc_kernel<<<(BB * 512 * 32 + 255) / 256, 256>>>(pool, 1024, fw1, nullptr, fg1, fbt1, f1, 512, 0);
    fc_kernel<<<(BB * 256 * 32 + 255) / 256, 256>>>(f1, 512, fw2, fb2, fg2, fbt2, f2, 256, 1);
    fc_kernel<<<(BB * 3 * 32 + 255) / 256, 256>>>(f2, 256, fw3, fb3, nullptr, nullptr,
                                                  (float*)d_out, 3, 2);
    (void)out_size;
}